// round 11
// baseline (speedup 1.0000x reference)
#include <cuda_runtime.h>
#include <cuda_fp16.h>

#define NT 256
#define P 2

// device scratch (static — no allocation)
__device__ __half w16g[32 * 8 * 256];        // 128 KB, same (i,c,m) layout as w
__device__ float  xTg[8 * 256 * 256];        // 2 MB, xT[b][hw][i*8+c]

// main-kernel smem layout (bytes, 16B aligned)
//  vB   : half [64][264]  rows p*32+i, 132 half2 words/row   33792
//  xs   : float[P][256]                                       2048
//  route: float[P][16][32] (transposed)                       4096
//  logit: float[P][32][17]                                    4352
//  act2 : half2[P][128]                                       1024
//  actF : float[P][256]                                       2048
#define OFF_VB     0
#define OFF_XS     33792
#define OFF_ROUTE  35840
#define OFF_LOGIT  39936
#define OFF_ACT    44288
#define OFF_ACTF   45312
#define SMEM_BYTES 47360
#define VROW 132                  // half2 words per vote row

// ---------------- prologue: w -> fp16, x -> transposed ----------------
__global__ __launch_bounds__(256)
void caps_prologue(const float* __restrict__ x, const float* __restrict__ w) {
    __shared__ float tile[32 * 257];
    const int blk = blockIdx.x;              // 64 blocks
    const int t   = threadIdx.x;

    // weight conversion: 64 blocks x 1024 elems
    {
        const int base = blk * 1024 + t * 4;
        const float4 wv = *(const float4*)(w + base);
        *(__half2*)(w16g + base)     = __floats2half2_rn(wv.x, wv.y);
        *(__half2*)(w16g + base + 2) = __floats2half2_rn(wv.z, wv.w);
    }

    // x transpose: block = (b, hw-tile of 32)
    const int b   = blk >> 3;
    const int hw0 = (blk & 7) << 5;
    const int wrp = t >> 5, l = t & 31;
    const int rowb = wrp * 4 + (l >> 3);     // 0..31
    const int hwq  = (l & 7) * 4;
    #pragma unroll
    for (int k = 0; k < 8; ++k) {
        const int row = k * 32 + rowb;       // ic index 0..255
        const float4 v = *(const float4*)(x + b * 65536 + row * 256 + hw0 + hwq);
        tile[(hwq + 0) * 257 + row] = v.x;
        tile[(hwq + 1) * 257 + row] = v.y;
        tile[(hwq + 2) * 257 + row] = v.z;
        tile[(hwq + 3) * 257 + row] = v.w;
    }
    __syncthreads();
    #pragma unroll 4
    for (int hw = 0; hw < 32; ++hw)
        xTg[(b * 256 + hw0 + hw) * 256 + t] = tile[hw * 257 + t];
}

// ---------------- main kernel ----------------
__global__ __launch_bounds__(NT, 4)
void caps_route_kernel(const float* __restrict__ bias, float* __restrict__ out) {
    extern __shared__ char smem[];
    float*   xs     = (float*)  (smem + OFF_XS);
    float*   routeT = (float*)  (smem + OFF_ROUTE);
    float*   logit  = (float*)  (smem + OFF_LOGIT);
    __half2* act2   = (__half2*)(smem + OFF_ACT);
    float*   actF   = (float*)  (smem + OFF_ACTF);
    __half2* vB2    = (__half2*)(smem + OFF_VB);       // word = row*VROW + m/2

    const int tid  = threadIdx.x;
    const int pix0 = blockIdx.x * P;
    const int b    = pix0 >> 8;
    const int hw0  = pix0 & 255;

    // x slice from transposed layout: 2 contiguous 1KB rows
    xs[tid]       = xTg[(b * 256 + hw0) * 256 + tid];
    xs[256 + tid] = xTg[(b * 256 + hw0 + 1) * 256 + tid];
    for (int k = tid; k < P * 544; k += NT) logit[k] = 0.f;
    for (int k = tid; k < P * 512; k += NT) routeT[k] = 0.0625f;  // softmax(0)
    __syncthreads();

    // ---- votes: thread = (i-group of 8, m-quad); fp16 weights ----
    {
        const int iq = tid >> 6;
        const int mq = (tid & 63) << 2;
        #pragma unroll
        for (int ii = 0; ii < 8; ++ii) {
            const int i = (iq << 3) + ii;
            float xv0[8], xv1[8];
            *(float4*)(xv0)     = *(const float4*)(xs + i * 8);
            *(float4*)(xv0 + 4) = *(const float4*)(xs + i * 8 + 4);
            *(float4*)(xv1)     = *(const float4*)(xs + 256 + i * 8);
            *(float4*)(xv1 + 4) = *(const float4*)(xs + 256 + i * 8 + 4);
            const __half2* wp = (const __half2*)w16g + (i << 10) + (mq >> 1);
            float4 a0 = make_float4(0.f, 0.f, 0.f, 0.f);
            float4 a1 = make_float4(0.f, 0.f, 0.f, 0.f);
            #pragma unroll
            for (int c = 0; c < 8; ++c) {
                const uint2 wraw = *(const uint2*)(wp + c * 128);
                const float2 wlo = __half22float2(*(const __half2*)&wraw.x);
                const float2 whi = __half22float2(*(const __half2*)&wraw.y);
                a0.x += xv0[c] * wlo.x; a0.y += xv0[c] * wlo.y;
                a0.z += xv0[c] * whi.x; a0.w += xv0[c] * whi.y;
                a1.x += xv1[c] * wlo.x; a1.y += xv1[c] * wlo.y;
                a1.z += xv1[c] * whi.x; a1.w += xv1[c] * whi.y;
            }
            __half2 h0 = __floats2half2_rn(a0.x, a0.y);
            __half2 h1 = __floats2half2_rn(a0.z, a0.w);
            uint2 s0; s0.x = *(unsigned*)&h0; s0.y = *(unsigned*)&h1;
            *(uint2*)(vB2 + i * VROW + (mq >> 1)) = s0;
            __half2 h2 = __floats2half2_rn(a1.x, a1.y);
            __half2 h3 = __floats2half2_rn(a1.z, a1.w);
            uint2 s1; s1.x = *(unsigned*)&h2; s1.y = *(unsigned*)&h3;
            *(uint2*)(vB2 + (32 + i) * VROW + (mq >> 1)) = s1;
        }
    }
    __syncthreads();

    // ---- routing: thread owns pixel pp, m-pair (2tt, 2tt+1) ----
    const int pp = tid >> 7;
    const int tt = tid & 127;
    const int oo = tt >> 3;
    const float2 bv = *(const float2*)(bias + (tt << 1));

    __half2 v2[32];   // this thread's vote column, reused all 3 iters
    {
        const __half2* vcol = vB2 + pp * 32 * VROW + tt;
        #pragma unroll
        for (int i = 0; i < 32; ++i) v2[i] = vcol[i * VROW];
    }

    float a0f = 0.f, a1f = 0.f;

    #pragma unroll 1
    for (int r = 0; r < 3; ++r) {
        if (r > 0) {
            if (tid < 64) {
                const int p = tid >> 5, i = tid & 31;
                const float* lr = logit + p * 544 + i * 17;
                float mx = lr[0];
                #pragma unroll
                for (int o = 1; o < 16; ++o) mx = fmaxf(mx, lr[o]);
                float e[16], s = 0.f;
                #pragma unroll
                for (int o = 0; o < 16; ++o) { e[o] = __expf(lr[o] - mx); s += e[o]; }
                const float inv = __fdividef(1.f, s);
                float* rr = routeT + p * 512 + i;
                #pragma unroll
                for (int o = 0; o < 16; ++o) rr[o * 32] = e[o] * inv;
            }
            __syncthreads();
        }

        // preact from register votes
        float acc0 = bv.x, acc1 = bv.y;
        const float* rp = routeT + pp * 512 + oo * 32;
        #pragma unroll
        for (int ii = 0; ii < 8; ++ii) {
            const float4 rr = *(const float4*)(rp + ii * 4);
            const float2 q0 = __half22float2(v2[ii * 4 + 0]);
            const float2 q1 = __half22float2(v2[ii * 4 + 1]);
            const float2 q2 = __half22float2(v2[ii * 4 + 2]);
            const float2 q3 = __half22float2(v2[ii * 4 + 3]);
            acc0 += rr.x * q0.x + rr.y * q1.x + rr.z * q2.x + rr.w * q3.x;
            acc1 += rr.x * q0.y + rr.y * q1.y + rr.z * q2.y + rr.w * q3.y;
        }
        float ss = acc0 * acc0 + acc1 * acc1;
        ss += __shfl_xor_sync(0xffffffffu, ss, 4);
        ss += __shfl_xor_sync(0xffffffffu, ss, 2);
        ss += __shfl_xor_sync(0xffffffffu, ss, 1);
        const float sc = sqrtf(ss) / (1.f + ss);
        a0f = acc0 * sc;
        a1f = acc1 * sc;
        act2[pp * 128 + tt] = __floats2half2_rn(a0f, a1f);
        if (r == 2)
            *(float2*)(actF + pp * 256 + (tt << 1)) = make_float2(a0f, a1f);
        __syncthreads();

        if (r < 2) {
            // distances[p][i][o] = sum_h votes[m=o*16+h][i] * act[m], vectorized
            #pragma unroll
            for (int k = 0; k < 4; ++k) {
                const int idx = tid + (k << 8);
                const int p   = idx >> 9;
                const int o   = (idx >> 5) & 15;
                const int i   = idx & 31;
                const uint4* vq4 = (const uint4*)(vB2 + (p * 32 + i) * VROW + (o << 3));
                const uint4* aq4 = (const uint4*)(act2 + p * 128 + (o << 3));
                const uint4 qa = vq4[0], qb = vq4[1];
                const uint4 ra = aq4[0], rb = aq4[1];
                float d = 0.f;
                {
                    const float2 v0 = __half22float2(*(const __half2*)&qa.x), u0 = __half22float2(*(const __half2*)&ra.x);
                    const float2 v1 = __half22float2(*(const __half2*)&qa.y), u1 = __half22float2(*(const __half2*)&ra.y);
                    const float2 v2_ = __half22float2(*(const __half2*)&qa.z), u2 = __half22float2(*(const __half2*)&ra.z);
                    const float2 v3 = __half22float2(*(const __half2*)&qa.w), u3 = __half22float2(*(const __half2*)&ra.w);
                    d += v0.x * u0.x + v0.y * u0.y + v1.x * u1.x + v1.y * u1.y;
                    d += v2_.x * u2.x + v2_.y * u2.y + v3.x * u3.x + v3.y * u3.y;
                }
                {
                    const float2 v0 = __half22float2(*(const __half2*)&qb.x), u0 = __half22float2(*(const __half2*)&rb.x);
                    const float2 v1 = __half22float2(*(const __half2*)&qb.y), u1 = __half22float2(*(const __half2*)&rb.y);
                    const float2 v2_ = __half22float2(*(const __half2*)&qb.z), u2 = __half22float2(*(const __half2*)&rb.z);
                    const float2 v3 = __half22float2(*(const __half2*)&qb.w), u3 = __half22float2(*(const __half2*)&rb.w);
                    d += v0.x * u0.x + v0.y * u0.y + v1.x * u1.x + v1.y * u1.y;
                    d += v2_.x * u2.x + v2_.y * u2.y + v3.x * u3.x + v3.y * u3.y;
                }
                logit[p * 544 + i * 17 + o] += d;
            }
            __syncthreads();
        }
    }

    // ---- out: thread = m, both pixels as one float2 (fp32-exact) ----
    {
        const int m = tid;
        const float2 ov = make_float2(actF[m], actF[256 + m]);
        *(float2*)(out + (((b << 8) + m) << 8) + hw0) = ov;
    }
}

extern "C" void kernel_launch(void* const* d_in, const int* in_sizes, int n_in,
                              void* d_out, int out_size) {
    const float* x    = (const float*)d_in[0];
    const float* w    = (const float*)d_in[1];
    const float* bias = (const float*)d_in[2];
    float* out        = (float*)d_out;

    static bool attr_set = false;
    if (!attr_set) {
        cudaFuncSetAttribute(caps_route_kernel,
                             cudaFuncAttributeMaxDynamicSharedMemorySize, SMEM_BYTES);
        attr_set = true;
    }

    caps_prologue<<<64, 256>>>(x, w);
    caps_route_kernel<<<(8 * 256) / P, NT, SMEM_BYTES>>>(bias, out);
}

// round 13
// speedup vs baseline: 1.5541x; 1.5541x over previous
#include <cuda_runtime.h>
#include <cuda_fp16.h>

#define NT 256
#define P 2

// smem layout (bytes, 16B aligned)
//  vB   : half [64][264]  rows p*32+i, VROW=132 half2 words/row  33792
//  xs   : float[P][256]                                           2048
//  route: float[P][16][32] (transposed)                           4096
//  logit: float[P][32][17]                                        4352
//  act2 : half2[P][128]                                           1024
//  actF : float[P][256]                                           2048
#define OFF_VB     0
#define OFF_XS     33792
#define OFF_ROUTE  35840
#define OFF_LOGIT  39936
#define OFF_ACT    44288
#define OFF_ACTF   45312
#define SMEM_BYTES 47360
#define VROW 132

__global__ __launch_bounds__(NT, 4)
void caps_route_kernel(const float* __restrict__ x,
                       const float* __restrict__ w,
                       const float* __restrict__ bias,
                       float* __restrict__ out) {
    extern __shared__ char smem[];
    float*   xs     = (float*)  (smem + OFF_XS);
    float*   routeT = (float*)  (smem + OFF_ROUTE);
    float*   logit  = (float*)  (smem + OFF_LOGIT);
    __half2* act2   = (__half2*)(smem + OFF_ACT);
    float*   actF   = (float*)  (smem + OFF_ACTF);
    __half2* vB2    = (__half2*)(smem + OFF_VB);   // word = row*VROW + m/2

    const int tid  = threadIdx.x;
    const int pix0 = blockIdx.x * P;
    const int b    = pix0 >> 8;
    const int hw0  = pix0 & 255;

    // ---- x load: thread = (i,c) row; 2 adjacent pixels as float2 ----
    {
        const float2 v = *(const float2*)(x + ((((b << 8) + tid) << 8) + hw0));
        xs[tid]       = v.x;
        xs[256 + tid] = v.y;
    }
    for (int k = tid; k < P * 544; k += NT) logit[k] = 0.f;
    for (int k = tid; k < P * 512; k += NT) routeT[k] = 0.0625f;  // softmax(0)
    __syncthreads();

    // ---- votes: thread = (i-group of 8, m-quad); fp32 weights, float4 loads ----
    {
        const int iq = tid >> 6;            // i = iq*8 .. iq*8+7
        const int mq = (tid & 63) << 2;     // m quad base
        #pragma unroll
        for (int ii = 0; ii < 8; ++ii) {
            const int i = (iq << 3) + ii;
            const float4 xa0 = *(const float4*)(xs + i * 8);
            const float4 xb0 = *(const float4*)(xs + i * 8 + 4);
            const float4 xa1 = *(const float4*)(xs + 256 + i * 8);
            const float4 xb1 = *(const float4*)(xs + 256 + i * 8 + 4);
            const float* wp = w + (i << 11) + mq;
            float4 a0 = make_float4(0.f, 0.f, 0.f, 0.f);
            float4 a1 = make_float4(0.f, 0.f, 0.f, 0.f);
            #pragma unroll
            for (int c = 0; c < 8; ++c) {
                const float4 wv = *(const float4*)(wp + (c << 8));
                const float x0 = ((c < 4) ? (&xa0.x)[c] : (&xb0.x)[c - 4]);
                const float x1 = ((c < 4) ? (&xa1.x)[c] : (&xb1.x)[c - 4]);
                a0.x += x0 * wv.x; a0.y += x0 * wv.y; a0.z += x0 * wv.z; a0.w += x0 * wv.w;
                a1.x += x1 * wv.x; a1.y += x1 * wv.y; a1.z += x1 * wv.z; a1.w += x1 * wv.w;
            }
            __half2 h0 = __floats2half2_rn(a0.x, a0.y);
            __half2 h1 = __floats2half2_rn(a0.z, a0.w);
            uint2 s0; s0.x = *(unsigned*)&h0; s0.y = *(unsigned*)&h1;
            *(uint2*)(vB2 + i * VROW + (mq >> 1)) = s0;
            __half2 h2 = __floats2half2_rn(a1.x, a1.y);
            __half2 h3 = __floats2half2_rn(a1.z, a1.w);
            uint2 s1; s1.x = *(unsigned*)&h2; s1.y = *(unsigned*)&h3;
            *(uint2*)(vB2 + (32 + i) * VROW + (mq >> 1)) = s1;
        }
    }
    __syncthreads();

    // ---- routing: thread owns pixel pp, m-pair (2tt, 2tt+1) ----
    const int pp = tid >> 7;
    const int tt = tid & 127;
    const int oo = tt >> 3;
    const float2 bv = *(const float2*)(bias + (tt << 1));

    __half2 v2[32];   // this thread's vote column, reused across all 3 iters
    {
        const __half2* vcol = vB2 + pp * 32 * VROW + tt;
        #pragma unroll
        for (int i = 0; i < 32; ++i) v2[i] = vcol[i * VROW];
    }

    float a0f = 0.f, a1f = 0.f;

    #pragma unroll 1
    for (int r = 0; r < 3; ++r) {
        if (r > 0) {
            if (tid < 64) {
                const int p = tid >> 5, i = tid & 31;
                const float* lr = logit + p * 544 + i * 17;
                float mx = lr[0];
                #pragma unroll
                for (int o = 1; o < 16; ++o) mx = fmaxf(mx, lr[o]);
                float e[16], s = 0.f;
                #pragma unroll
                for (int o = 0; o < 16; ++o) { e[o] = __expf(lr[o] - mx); s += e[o]; }
                const float inv = __fdividef(1.f, s);
                float* rr = routeT + p * 512 + i;
                #pragma unroll
                for (int o = 0; o < 16; ++o) rr[o * 32] = e[o] * inv;
            }
            __syncthreads();
        }

        // preact from register votes + route broadcasts
        float acc0 = bv.x, acc1 = bv.y;
        const float* rp = routeT + pp * 512 + oo * 32;
        #pragma unroll
        for (int ii = 0; ii < 8; ++ii) {
            const float4 rr = *(const float4*)(rp + ii * 4);
            const float2 q0 = __half22float2(v2[ii * 4 + 0]);
            const float2 q1 = __half22float2(v2[ii * 4 + 1]);
            const float2 q2 = __half22float2(v2[ii * 4 + 2]);
            const float2 q3 = __half22float2(v2[ii * 4 + 3]);
            acc0 += rr.x * q0.x + rr.y * q1.x + rr.z * q2.x + rr.w * q3.x;
            acc1 += rr.x * q0.y + rr.y * q1.y + rr.z * q2.y + rr.w * q3.y;
        }
        float ss = acc0 * acc0 + acc1 * acc1;
        ss += __shfl_xor_sync(0xffffffffu, ss, 4);
        ss += __shfl_xor_sync(0xffffffffu, ss, 2);
        ss += __shfl_xor_sync(0xffffffffu, ss, 1);
        const float sc = sqrtf(ss) / (1.f + ss);
        a0f = acc0 * sc;
        a1f = acc1 * sc;
        act2[pp * 128 + tt] = __floats2half2_rn(a0f, a1f);
        if (r == 2)
            *(float2*)(actF + pp * 256 + (tt << 1)) = make_float2(a0f, a1f);
        __syncthreads();

        if (r < 2) {
            // distances[p][i][o] = sum_h votes[m=o*16+h][i] * act[m] — LDS.128
            #pragma unroll
            for (int k = 0; k < 4; ++k) {
                const int idx = tid + (k << 8);
                const int p   = idx >> 9;
                const int o   = (idx >> 5) & 15;
                const int i   = idx & 31;
                const uint4* vq4 = (const uint4*)(vB2 + (p * 32 + i) * VROW + (o << 3));
                const uint4* aq4 = (const uint4*)(act2 + p * 128 + (o << 3));
                const uint4 qa = vq4[0], qb = vq4[1];
                const uint4 ra = aq4[0], rb = aq4[1];
                float d = 0.f;
                {
                    const float2 v0 = __half22float2(*(const __half2*)&qa.x), u0 = __half22float2(*(const __half2*)&ra.x);
                    const float2 v1 = __half22float2(*(const __half2*)&qa.y), u1 = __half22float2(*(const __half2*)&ra.y);
                    const float2 vc = __half22float2(*(const __half2*)&qa.z), u2 = __half22float2(*(const __half2*)&ra.z);
                    const float2 v3 = __half22float2(*(const __half2*)&qa.w), u3 = __half22float2(*(const __half2*)&ra.w);
                    d += v0.x * u0.x + v0.y * u0.y + v1.x * u1.x + v1.y * u1.y;
                    d += vc.x * u2.x + vc.y * u2.y + v3.x * u3.x + v3.y * u3.y;
                }
                {
                    const float2 v0 = __half22float2(*(const __half2*)&qb.x), u0 = __half22float2(*(const __half2*)&rb.x);
                    const float2 v1 = __half22float2(*(const __half2*)&qb.y), u1 = __half22float2(*(const __half2*)&rb.y);
                    const float2 vc = __half22float2(*(const __half2*)&qb.z), u2 = __half22float2(*(const __half2*)&rb.z);
                    const float2 v3 = __half22float2(*(const __half2*)&qb.w), u3 = __half22float2(*(const __half2*)&rb.w);
                    d += v0.x * u0.x + v0.y * u0.y + v1.x * u1.x + v1.y * u1.y;
                    d += vc.x * u2.x + vc.y * u2.y + v3.x * u3.x + v3.y * u3.y;
                }
                logit[p * 544 + i * 17 + o] += d;
            }
            __syncthreads();
        }
    }

    // ---- out: thread = m, both pixels as one float2 (fp32-exact) ----
    {
        const float2 ov = make_float2(actF[tid], actF[256 + tid]);
        *(float2*)(out + (((b << 8) + tid) << 8) + hw0) = ov;
    }
}

extern "C" void kernel_launch(void* const* d_in, const int* in_sizes, int n_in,
                              void* d_out, int out_size) {
    const float* x    = (const float*)d_in[0];
    const float* w    = (const float*)d_in[1];
    const float* bias = (const float*)d_in[2];
    float* out        = (float*)d_out;

    static bool attr_set = false;
    if (!attr_set) {
        cudaFuncSetAttribute(caps_route_kernel,
                             cudaFuncAttributeMaxDynamicSharedMemorySize, SMEM_BYTES);
        attr_set = true;
    }

    caps_route_kernel<<<(8 * 256) / P, NT, SMEM_BYTES>>>(x, w, bias, out);
}

// round 15
// speedup vs baseline: 1.7651x; 1.1358x over previous
#include <cuda_runtime.h>
#include <cuda_fp16.h>

#define NT 256
#define P 2
#define VROW 132                 // half2 words per vote row (528 B, 16B-aligned)

// device scratch: fp16 weights, same (i*8+c)*256+m layout (128 KB)
__device__ __half w16g[32 * 8 * 256];

// smem layout (bytes, 16B aligned)
//  vB   : half [64][264]  rows p*32+i                    33792
//  xs2  : half2[P][256]   (x duplicated into both lanes)  2048
//  route: float[P][16][32] (transposed)                   4096
//  logit: float[P][32][17]                                4352
//  act2 : half2[P][128]                                   1024
//  actF : float[P][256]                                   2048
#define OFF_VB     0
#define OFF_XS     33792
#define OFF_ROUTE  35840
#define OFF_LOGIT  39936
#define OFF_ACT    44288
#define OFF_ACTF   45312
#define SMEM_BYTES 47360

__global__ __launch_bounds__(256)
void caps_w16(const float* __restrict__ w) {
    const int idx = (blockIdx.x * 256 + threadIdx.x) * 4;
    const float4 v = *(const float4*)(w + idx);
    __half2 h01 = __floats2half2_rn(v.x, v.y);
    __half2 h23 = __floats2half2_rn(v.z, v.w);
    uint2 s; s.x = *(unsigned*)&h01; s.y = *(unsigned*)&h23;
    *(uint2*)(w16g + idx) = s;
}

__global__ __launch_bounds__(NT, 4)
void caps_route_kernel(const float* __restrict__ x,
                       const float* __restrict__ bias,
                       float* __restrict__ out) {
    extern __shared__ char smem[];
    __half2* xs2    = (__half2*)(smem + OFF_XS);
    float*   routeT = (float*)  (smem + OFF_ROUTE);
    float*   logit  = (float*)  (smem + OFF_LOGIT);
    __half2* act2   = (__half2*)(smem + OFF_ACT);
    float*   actF   = (float*)  (smem + OFF_ACTF);
    __half2* vB2    = (__half2*)(smem + OFF_VB);   // word = row*VROW + m/2

    const int tid  = threadIdx.x;
    const int lane = tid & 31;
    const int pix0 = blockIdx.x * P;
    const int b    = pix0 >> 8;
    const int hw0  = pix0 & 255;

    // ---- x load: thread = (i,c); store as duplicated half2 ----
    {
        const float2 v = *(const float2*)(x + ((((b << 8) + tid) << 8) + hw0));
        const __half h0 = __float2half_rn(v.x);
        const __half h1 = __float2half_rn(v.y);
        xs2[tid]       = __half2half2(h0);
        xs2[256 + tid] = __half2half2(h1);
    }
    for (int k = tid; k < P * 544; k += NT) logit[k] = 0.f;
    __syncthreads();

    // ---- votes in half2: warp owns 4 i's, lane owns m-oct (8 m) ----
    {
        const int iw = tid >> 5;                     // warp = i-group of 4
        const uint4* wq = (const uint4*)w16g;        // uint4 = 8 halfs
        #pragma unroll
        for (int ii = 0; ii < 4; ++ii) {
            const int i = (iw << 2) + ii;
            unsigned xr0[8], xr1[8];
            *(uint4*)(xr0)     = *(const uint4*)(xs2 + i * 8);
            *(uint4*)(xr0 + 4) = *(const uint4*)(xs2 + i * 8 + 4);
            *(uint4*)(xr1)     = *(const uint4*)(xs2 + 256 + i * 8);
            *(uint4*)(xr1 + 4) = *(const uint4*)(xs2 + 256 + i * 8 + 4);
            __half2 a0[4], a1[4];
            #pragma unroll
            for (int j = 0; j < 4; ++j) { a0[j] = __half2half2(__ushort_as_half(0)); a1[j] = a0[j]; }
            #pragma unroll
            for (int c = 0; c < 8; ++c) {
                const uint4 wv = wq[((i << 3) + c) * 32 + lane];
                const __half2 w0 = *(const __half2*)&wv.x;
                const __half2 w1 = *(const __half2*)&wv.y;
                const __half2 w2 = *(const __half2*)&wv.z;
                const __half2 w3 = *(const __half2*)&wv.w;
                const __half2 x0 = *(const __half2*)&xr0[c];
                const __half2 x1 = *(const __half2*)&xr1[c];
                a0[0] = __hfma2(x0, w0, a0[0]); a0[1] = __hfma2(x0, w1, a0[1]);
                a0[2] = __hfma2(x0, w2, a0[2]); a0[3] = __hfma2(x0, w3, a0[3]);
                a1[0] = __hfma2(x1, w0, a1[0]); a1[1] = __hfma2(x1, w1, a1[1]);
                a1[2] = __hfma2(x1, w2, a1[2]); a1[3] = __hfma2(x1, w3, a1[3]);
            }
            *(uint4*)(vB2 + i * VROW + (lane << 2))        = *(uint4*)a0;
            *(uint4*)(vB2 + (32 + i) * VROW + (lane << 2)) = *(uint4*)a1;
        }
    }
    __syncthreads();

    // ---- routing: thread owns pixel pp, m-pair (2tt, 2tt+1) ----
    const int pp = tid >> 7;
    const int tt = tid & 127;
    const int oo = tt >> 3;
    const float2 bv = *(const float2*)(bias + (tt << 1));

    __half2 v2[32];
    {
        const __half2* vcol = vB2 + pp * 32 * VROW + tt;
        #pragma unroll
        for (int i = 0; i < 32; ++i) v2[i] = vcol[i * VROW];
    }

    float a0f = 0.f, a1f = 0.f;

    #pragma unroll 1
    for (int r = 0; r < 3; ++r) {
        float acc0 = bv.x, acc1 = bv.y;
        if (r == 0) {
            // route == 1/16 exactly (softmax of zero logits) — no smem
            float s0 = 0.f, s1 = 0.f;
            #pragma unroll
            for (int i = 0; i < 32; ++i) {
                const float2 q = __half22float2(v2[i]);
                s0 += q.x; s1 += q.y;
            }
            acc0 += 0.0625f * s0;
            acc1 += 0.0625f * s1;
        } else {
            if (tid < 64) {
                const int p = tid >> 5, i = tid & 31;
                const float* lr = logit + p * 544 + i * 17;
                float mx = lr[0];
                #pragma unroll
                for (int o = 1; o < 16; ++o) mx = fmaxf(mx, lr[o]);
                float e[16], s = 0.f;
                #pragma unroll
                for (int o = 0; o < 16; ++o) { e[o] = __expf(lr[o] - mx); s += e[o]; }
                const float inv = __fdividef(1.f, s);
                float* rr = routeT + p * 512 + i;
                #pragma unroll
                for (int o = 0; o < 16; ++o) rr[o * 32] = e[o] * inv;
            }
            __syncthreads();

            const float* rp = routeT + pp * 512 + oo * 32;
            #pragma unroll
            for (int ii = 0; ii < 8; ++ii) {
                const float4 rr = *(const float4*)(rp + ii * 4);
                const float2 q0 = __half22float2(v2[ii * 4 + 0]);
                const float2 q1 = __half22float2(v2[ii * 4 + 1]);
                const float2 q2 = __half22float2(v2[ii * 4 + 2]);
                const float2 q3 = __half22float2(v2[ii * 4 + 3]);
                acc0 += rr.x * q0.x + rr.y * q1.x + rr.z * q2.x + rr.w * q3.x;
                acc1 += rr.x * q0.y + rr.y * q1.y + rr.z * q2.y + rr.w * q3.y;
            }
        }
        float ss = acc0 * acc0 + acc1 * acc1;
        ss += __shfl_xor_sync(0xffffffffu, ss, 4);
        ss += __shfl_xor_sync(0xffffffffu, ss, 2);
        ss += __shfl_xor_sync(0xffffffffu, ss, 1);
        const float sc = sqrtf(ss) / (1.f + ss);
        a0f = acc0 * sc;
        a1f = acc1 * sc;
        act2[pp * 128 + tt] = __floats2half2_rn(a0f, a1f);
        if (r == 2)
            *(float2*)(actF + pp * 256 + (tt << 1)) = make_float2(a0f, a1f);
        __syncthreads();

        if (r < 2) {
            // distances via LDS.128 (conflict-free), accumulate into logits
            #pragma unroll
            for (int k = 0; k < 4; ++k) {
                const int idx = tid + (k << 8);
                const int p   = idx >> 9;
                const int o   = (idx >> 5) & 15;
                const int i   = idx & 31;
                const uint4* vq4 = (const uint4*)(vB2 + (p * 32 + i) * VROW + (o << 3));
                const uint4* aq4 = (const uint4*)(act2 + p * 128 + (o << 3));
                const uint4 qa = vq4[0], qb = vq4[1];
                const uint4 ra = aq4[0], rb = aq4[1];
                float d = 0.f;
                {
                    const float2 v0 = __half22float2(*(const __half2*)&qa.x), u0 = __half22float2(*(const __half2*)&ra.x);
                    const float2 v1 = __half22float2(*(const __half2*)&qa.y), u1 = __half22float2(*(const __half2*)&ra.y);
                    const float2 vc = __half22float2(*(const __half2*)&qa.z), u2 = __half22float2(*(const __half2*)&ra.z);
                    const float2 v3 = __half22float2(*(const __half2*)&qa.w), u3 = __half22float2(*(const __half2*)&ra.w);
                    d += v0.x * u0.x + v0.y * u0.y + v1.x * u1.x + v1.y * u1.y;
                    d += vc.x * u2.x + vc.y * u2.y + v3.x * u3.x + v3.y * u3.y;
                }
                {
                    const float2 v0 = __half22float2(*(const __half2*)&qb.x), u0 = __half22float2(*(const __half2*)&rb.x);
                    const float2 v1 = __half22float2(*(const __half2*)&qb.y), u1 = __half22float2(*(const __half2*)&rb.y);
                    const float2 vc = __half22float2(*(const __half2*)&qb.z), u2 = __half22float2(*(const __half2*)&rb.z);
                    const float2 v3 = __half22float2(*(const __half2*)&qb.w), u3 = __half22float2(*(const __half2*)&rb.w);
                    d += v0.x * u0.x + v0.y * u0.y + v1.x * u1.x + v1.y * u1.y;
                    d += vc.x * u2.x + vc.y * u2.y + v3.x * u3.x + v3.y * u3.y;
                }
                logit[p * 544 + i * 17 + o] += d;
            }
            __syncthreads();
        }
    }

    // ---- out: thread = m, both pixels as one float2 (fp32-exact) ----
    {
        const float2 ov = make_float2(actF[tid], actF[256 + tid]);
        *(float2*)(out + (((b << 8) + tid) << 8) + hw0) = ov;
    }
}

extern "C" void kernel_launch(void* const* d_in, const int* in_sizes, int n_in,
                              void* d_out, int out_size) {
    const float* x    = (const float*)d_in[0];
    const float* w    = (const float*)d_in[1];
    const float* bias = (const float*)d_in[2];
    float* out        = (float*)d_out;

    static bool attr_set = false;
    if (!attr_set) {
        cudaFuncSetAttribute(caps_route_kernel,
                             cudaFuncAttributeMaxDynamicSharedMemorySize, SMEM_BYTES);
        attr_set = true;
    }

    caps_w16<<<64, 256>>>(w);
    caps_route_kernel<<<(8 * 256) / P, NT, SMEM_BYTES>>>(x, bias, out);
}

// round 16
// speedup vs baseline: 1.9069x; 1.0804x over previous
#include <cuda_runtime.h>
#include <cuda_fp16.h>

#define NT 512
#define P 4
#define VROW 132                 // half2 words per vote row (528 B, 16B-aligned)

// device scratch: fp16 weights, layout (i*8+c)*256 + m (128 KB)
__device__ __half w16g[32 * 8 * 256];

// smem layout (bytes)
//  vB   : half2 [128 rows][132]  rows = px*32+i            67584
//  xs4  : uint4 [256]  per ic: 4 dup half2 (one per px)     4096
//  route: float [4][16][32] (transposed)                    8192
//  logit: float [4][32][17]                                 8704
//  act2 : half2 [4][128]                                    2048
//  actF : float [4][256]                                    4096
#define OFF_VB     0
#define OFF_XS4    67584
#define OFF_ROUTE  71680
#define OFF_LOGIT  79872
#define OFF_ACT    88576
#define OFF_ACTF   90624
#define SMEM_BYTES 94720

__global__ __launch_bounds__(256)
void caps_w16(const float* __restrict__ w) {
    const int idx = (blockIdx.x * 256 + threadIdx.x) * 4;
    const float4 v = *(const float4*)(w + idx);
    __half2 h01 = __floats2half2_rn(v.x, v.y);
    __half2 h23 = __floats2half2_rn(v.z, v.w);
    uint2 s; s.x = *(unsigned*)&h01; s.y = *(unsigned*)&h23;
    *(uint2*)(w16g + idx) = s;
}

__global__ __launch_bounds__(NT, 2)
void caps_route_kernel(const float* __restrict__ x,
                       const float* __restrict__ bias,
                       float* __restrict__ out) {
    extern __shared__ char smem[];
    uint4*   xs4    = (uint4*)  (smem + OFF_XS4);
    float*   routeT = (float*)  (smem + OFF_ROUTE);
    float*   logit  = (float*)  (smem + OFF_LOGIT);
    __half2* act2   = (__half2*)(smem + OFF_ACT);
    float*   actF   = (float*)  (smem + OFF_ACTF);
    __half2* vB2    = (__half2*)(smem + OFF_VB);   // word = row*VROW + m/2

    const int tid  = threadIdx.x;
    const int lane = tid & 31;
    const int wid  = tid >> 5;
    const int pix0 = blockIdx.x * P;               // 4 adjacent hw
    const int b    = pix0 >> 8;
    const int hw0  = pix0 & 255;                   // multiple of 4

    // ---- x load: thread = ic (i*8+c); 4 adjacent pixels as float4 ----
    if (tid < 256) {
        const float4 v = *(const float4*)(x + ((((b << 8) + tid) << 8) + hw0));
        __half2 d0 = __half2half2(__float2half_rn(v.x));
        __half2 d1 = __half2half2(__float2half_rn(v.y));
        __half2 d2 = __half2half2(__float2half_rn(v.z));
        __half2 d3 = __half2half2(__float2half_rn(v.w));
        uint4 s;
        s.x = *(unsigned*)&d0; s.y = *(unsigned*)&d1;
        s.z = *(unsigned*)&d2; s.w = *(unsigned*)&d3;
        xs4[tid] = s;
    }
    for (int k = tid; k < 4 * 544; k += NT) logit[k] = 0.f;
    __syncthreads();

    // ---- votes in half2: warp owns i-pair, lane owns m-oct, 4 pixels at once ----
    {
        const uint4* wq = (const uint4*)w16g;      // index ic*32 + lane
        #pragma unroll
        for (int ii = 0; ii < 2; ++ii) {
            const int i = (wid << 1) + ii;
            __half2 a[4][4];
            #pragma unroll
            for (int px = 0; px < 4; ++px)
                #pragma unroll
                for (int j = 0; j < 4; ++j)
                    a[px][j] = __half2half2(__ushort_as_half(0));
            #pragma unroll
            for (int c = 0; c < 8; ++c) {
                const uint4 xv = xs4[(i << 3) + c];
                const uint4 wv = wq[(((i << 3) + c) << 5) + lane];
                const __half2 w0 = *(const __half2*)&wv.x;
                const __half2 w1 = *(const __half2*)&wv.y;
                const __half2 w2 = *(const __half2*)&wv.z;
                const __half2 w3 = *(const __half2*)&wv.w;
                const __half2 x0 = *(const __half2*)&xv.x;
                const __half2 x1 = *(const __half2*)&xv.y;
                const __half2 x2 = *(const __half2*)&xv.z;
                const __half2 x3 = *(const __half2*)&xv.w;
                a[0][0] = __hfma2(x0, w0, a[0][0]); a[0][1] = __hfma2(x0, w1, a[0][1]);
                a[0][2] = __hfma2(x0, w2, a[0][2]); a[0][3] = __hfma2(x0, w3, a[0][3]);
                a[1][0] = __hfma2(x1, w0, a[1][0]); a[1][1] = __hfma2(x1, w1, a[1][1]);
                a[1][2] = __hfma2(x1, w2, a[1][2]); a[1][3] = __hfma2(x1, w3, a[1][3]);
                a[2][0] = __hfma2(x2, w0, a[2][0]); a[2][1] = __hfma2(x2, w1, a[2][1]);
                a[2][2] = __hfma2(x2, w2, a[2][2]); a[2][3] = __hfma2(x2, w3, a[2][3]);
                a[3][0] = __hfma2(x3, w0, a[3][0]); a[3][1] = __hfma2(x3, w1, a[3][1]);
                a[3][2] = __hfma2(x3, w2, a[3][2]); a[3][3] = __hfma2(x3, w3, a[3][3]);
            }
            #pragma unroll
            for (int px = 0; px < 4; ++px) {
                uint4 s;
                s.x = *(unsigned*)&a[px][0]; s.y = *(unsigned*)&a[px][1];
                s.z = *(unsigned*)&a[px][2]; s.w = *(unsigned*)&a[px][3];
                *(uint4*)(vB2 + ((px << 5) + i) * VROW + (lane << 2)) = s;
            }
        }
    }
    __syncthreads();

    // ---- routing: thread owns pixel pp = tid>>7, m-pair (2tt, 2tt+1) ----
    const int pp = tid >> 7;
    const int tt = tid & 127;
    const int oo = tt >> 3;
    const float2 bv = *(const float2*)(bias + (tt << 1));

    __half2 v2[32];
    {
        const __half2* vcol = vB2 + pp * 32 * VROW + tt;
        #pragma unroll
        for (int i = 0; i < 32; ++i) v2[i] = vcol[i * VROW];
    }

    float a0f = 0.f, a1f = 0.f;

    #pragma unroll 1
    for (int r = 0; r < 3; ++r) {
        float acc0 = bv.x, acc1 = bv.y;
        if (r == 0) {
            // route == 1/16 (softmax of zero logits) — pure register path
            float s0 = 0.f, s1 = 0.f;
            #pragma unroll
            for (int i = 0; i < 32; ++i) {
                const float2 q = __half22float2(v2[i]);
                s0 += q.x; s1 += q.y;
            }
            acc0 += 0.0625f * s0;
            acc1 += 0.0625f * s1;
        } else {
            if (tid < 128) {
                const int p = tid >> 5, i = tid & 31;
                const float* lr = logit + p * 544 + i * 17;
                float mx = lr[0];
                #pragma unroll
                for (int o = 1; o < 16; ++o) mx = fmaxf(mx, lr[o]);
                float e[16], s = 0.f;
                #pragma unroll
                for (int o = 0; o < 16; ++o) { e[o] = __expf(lr[o] - mx); s += e[o]; }
                const float inv = __fdividef(1.f, s);
                float* rr = routeT + p * 512 + i;
                #pragma unroll
                for (int o = 0; o < 16; ++o) rr[o * 32] = e[o] * inv;
            }
            __syncthreads();

            const float* rp = routeT + pp * 512 + oo * 32;
            #pragma unroll
            for (int ii = 0; ii < 8; ++ii) {
                const float4 rr = *(const float4*)(rp + ii * 4);
                const float2 q0 = __half22float2(v2[ii * 4 + 0]);
                const float2 q1 = __half22float2(v2[ii * 4 + 1]);
                const float2 q2 = __half22float2(v2[ii * 4 + 2]);
                const float2 q3 = __half22float2(v2[ii * 4 + 3]);
                acc0 += rr.x * q0.x + rr.y * q1.x + rr.z * q2.x + rr.w * q3.x;
                acc1 += rr.x * q0.y + rr.y * q1.y + rr.z * q2.y + rr.w * q3.y;
            }
        }
        // squash over 16 h (8-lane group per o, 2 h per lane)
        float ss = acc0 * acc0 + acc1 * acc1;
        ss += __shfl_xor_sync(0xffffffffu, ss, 4);
        ss += __shfl_xor_sync(0xffffffffu, ss, 2);
        ss += __shfl_xor_sync(0xffffffffu, ss, 1);
        const float sc = sqrtf(ss) / (1.f + ss);
        a0f = acc0 * sc;
        a1f = acc1 * sc;
        act2[pp * 128 + tt] = __floats2half2_rn(a0f, a1f);
        if (r == 2)
            *(float2*)(actF + pp * 256 + (tt << 1)) = make_float2(a0f, a1f);
        __syncthreads();

        if (r < 2) {
            // distances[p][i][o] = sum_h v[m][i]*act[m] — LDS.128 + HFMA2
            #pragma unroll
            for (int k = 0; k < 4; ++k) {
                const int idx = tid + (k << 9);            // 0..2047
                const int p   = idx >> 9;
                const int o   = (idx >> 5) & 15;
                const int i   = idx & 31;
                const uint4* vq4 = (const uint4*)(vB2 + ((p << 5) + i) * VROW + (o << 3));
                const uint4* aq4 = (const uint4*)(act2 + (p << 7) + (o << 3));
                const uint4 qa = vq4[0], qb = vq4[1];
                const uint4 ra = aq4[0], rb = aq4[1];
                __half2 d2 = __half2half2(__ushort_as_half(0));
                d2 = __hfma2(*(const __half2*)&qa.x, *(const __half2*)&ra.x, d2);
                d2 = __hfma2(*(const __half2*)&qa.y, *(const __half2*)&ra.y, d2);
                d2 = __hfma2(*(const __half2*)&qa.z, *(const __half2*)&ra.z, d2);
                d2 = __hfma2(*(const __half2*)&qa.w, *(const __half2*)&ra.w, d2);
                d2 = __hfma2(*(const __half2*)&qb.x, *(const __half2*)&rb.x, d2);
                d2 = __hfma2(*(const __half2*)&qb.y, *(const __half2*)&rb.y, d2);
                d2 = __hfma2(*(const __half2*)&qb.z, *(const __half2*)&rb.z, d2);
                d2 = __hfma2(*(const __half2*)&qb.w, *(const __half2*)&rb.w, d2);
                const float2 df = __half22float2(d2);
                logit[p * 544 + i * 17 + o] += df.x + df.y;
            }
            __syncthreads();
        }
    }

    // ---- out: thread = m, all 4 pixels as one float4 (fp32-exact) ----
    if (tid < 256) {
        const float4 ov = make_float4(actF[tid], actF[256 + tid],
                                      actF[512 + tid], actF[768 + tid]);
        *(float4*)(out + (((b << 8) + tid) << 8) + hw0) = ov;
    }
}

extern "C" void kernel_launch(void* const* d_in, const int* in_sizes, int n_in,
                              void* d_out, int out_size) {
    const float* x    = (const float*)d_in[0];
    const float* w    = (const float*)d_in[1];
    const float* bias = (const float*)d_in[2];
    float* out        = (float*)d_out;

    static bool attr_set = false;
    if (!attr_set) {
        cudaFuncSetAttribute(caps_route_kernel,
                             cudaFuncAttributeMaxDynamicSharedMemorySize, SMEM_BYTES);
        attr_set = true;
    }

    caps_w16<<<64, 256>>>(w);
    caps_route_kernel<<<(8 * 256) / P, NT, SMEM_BYTES>>>(x, bias, out);
}